// round 6
// baseline (speedup 1.0000x reference)
#include <cuda_runtime.h>
#include <cstdint>

#define WD 128
#define HT 128
#define NB 8
#define NC 16
#define HW (HT*WD)
#define CHW (NC*HW)
#define HO 127
#define WO 127
#define TR 6            // output rows per strip
#define NSTRIP 22       // ceil(127/6)
#define CSPLIT 4
#define CPER (NC/CSPLIT)
#define NCELLS 12

typedef unsigned long long ull;

__device__ __forceinline__ ull pack2(float x, float y) {
    ull r; asm("mov.b64 %0, {%1, %2};" : "=l"(r) : "f"(x), "f"(y)); return r;
}
__device__ __forceinline__ void unpack2(float& x, float& y, ull v) {
    asm("mov.b64 {%0, %1}, %2;" : "=f"(x), "=f"(y) : "l"(v));
}
__device__ __forceinline__ ull fma2(ull a, ull b, ull c) {
    ull d; asm("fma.rn.f32x2 %0, %1, %2, %3;" : "=l"(d) : "l"(a), "l"(b), "l"(c)); return d;
}
__device__ __forceinline__ ull add2(ull a, ull b) {
    ull d; asm("add.rn.f32x2 %0, %1, %2;" : "=l"(d) : "l"(a), "l"(b)); return d;
}
__device__ __forceinline__ void lds_row(ull& lo, ull& hi, unsigned addr) {
    asm volatile("ld.shared.v2.u64 {%0, %1}, [%2];" : "=l"(lo), "=l"(hi) : "r"(addr));
}

__global__ void __launch_bounds__(256, 5) kan_fused_kernel(
    const float* __restrict__ x,
    const float* __restrict__ base_weight,
    const float* __restrict__ spline_weight,
    const float* __restrict__ spline_scaler,
    const float* __restrict__ grid,
    float* __restrict__ out)
{
    // Per-lane-replicated power-basis table: cell t (0..10):
    // spline(u) = A + B u + C u^2 + D u^3 per tap. Cell 11 = zeros.
    __shared__ float4 tab[NCELLS * 4 * 32];      // 24.5 KB
    __shared__ float4 staging[NCELLS * 4];
    // Tap planes for this strip's 7 eval rows (14.3 KB).
    __shared__ float sa0[TR + 1][WD];
    __shared__ float sa1[TR + 1][WD];
    __shared__ float sa2[TR + 1][WD];
    __shared__ float sa3[TR + 1][WD];

    const int tid = threadIdx.x;

    // ── Stage 1: compute 48 coefficient float4s once ──
    if (tid < NCELLS * 4) {
        const int t = tid >> 2;
        const int k = tid & 3;
        float4 val = make_float4(0.f, 0.f, 0.f, 0.f);
        if (t <= 10) {
            float o[4];
#pragma unroll
            for (int f = 0; f < 4; f++) {
                const float sc = spline_scaler[f];
                float c[4];
#pragma unroll
                for (int jj = 0; jj < 4; jj++) {
                    const int idx = t - 3 + jj;
                    c[jj] = (idx >= 0 && idx < 8)
                          ? spline_weight[f * 8 + idx] * sc : 0.f;
                }
                float r;
                if (k == 0)      r = (c[0] + 4.f * c[1] + c[2]) * (1.f / 6.f);
                else if (k == 1) r = (c[2] - c[0]) * 0.5f;
                else if (k == 2) r = (c[0] - 2.f * c[1] + c[2]) * 0.5f;
                else             r = (3.f * (c[1] - c[2]) + c[3] - c[0]) * (1.f / 6.f);
                o[f] = r;
            }
            val = make_float4(o[0], o[1], o[2], o[3]);
        }
        staging[tid] = val;
    }
    __syncthreads();
    // ── Stage 2: replicate across lanes ──
#pragma unroll
    for (int e = tid; e < NCELLS * 4 * 32; e += 256)
        tab[e] = staging[e >> 5];
    __syncthreads();

    const float bw0 = __ldg(base_weight + 0);
    const float bw1 = __ldg(base_weight + 1);
    const float bw2 = __ldg(base_weight + 2);
    const float bw3 = __ldg(base_weight + 3);
    const float g0   = __ldg(grid + 0);
    const float invh = 1.0f / (__ldg(grid + 1) - g0);
    const float off0 = -g0 * invh;

    const ull bw01 = pack2(bw0, bw1);
    const ull bw23 = pack2(bw2, bw3);

    const int r0  = blockIdx.x * TR;
    const int b   = blockIdx.y;
    const int ch0 = blockIdx.z * CPER;

    const unsigned tab_base =
        (unsigned)__cvta_generic_to_shared(tab) + (unsigned)((tid & 31) * 16);

    // ── Eval: 7 rows x 128 cols, CPER channels summed ──
    for (int e = tid; e < (TR + 1) * WD; e += 256) {
        const int rl  = e >> 7;
        const int c   = e & (WD - 1);
        const int row = r0 + rl;

        ull acc01 = 0ull, acc23 = 0ull;
        if (row < HT) {
            const float* xp = x + b * CHW + ch0 * HW + row * WD + c;
            float v[CPER];
#pragma unroll
            for (int q = 0; q < CPER; q++)          // front-batched: MLP=CPER
                v[q] = __ldg(xp + q * HW);

#pragma unroll
            for (int q = 0; q < CPER; q++) {
                const float vv = v[q];
                const float pp = fmaf(vv, invh, off0);
                const float fc = floorf(pp);
                const float u  = pp - fc;
                const int cell = (int)fc;
                const int cb   = ((unsigned)cell <= 10u) ? cell : 11;

                const unsigned a = tab_base + ((unsigned)cb << 11);
                ull A01, A23, B01, B23, C01, C23, D01, D23;
                lds_row(A01, A23, a);
                lds_row(B01, B23, a + 512);
                lds_row(C01, C23, a + 1024);
                lds_row(D01, D23, a + 1536);

                const ull u2  = pack2(u, u);
                const ull t01 = fma2(fma2(fma2(D01, u2, C01), u2, B01), u2, A01);
                const ull t23 = fma2(fma2(fma2(D23, u2, C23), u2, B23), u2, A23);

                const float s = __fdividef(vv, 1.f + __expf(-vv));
                const ull s2 = pack2(s, s);
                acc01 = fma2(s2, bw01, acc01);
                acc23 = fma2(s2, bw23, acc23);
                acc01 = add2(acc01, t01);
                acc23 = add2(acc23, t23);
            }
        }
        float a0, a1, a2, a3;
        unpack2(a0, a1, acc01);
        unpack2(a2, a3, acc23);
        sa0[rl][c] = a0;
        sa1[rl][c] = a1;
        sa2[rl][c] = a2;
        sa3[rl][c] = a3;
    }

    __syncthreads();

    // ── Combine from smem, one atomic per output per channel-split ──
#pragma unroll
    for (int o = tid; o < TR * WD; o += 256) {
        const int rl = o >> 7;
        const int c  = o & (WD - 1);
        const int r  = r0 + rl;
        if (r < HO && c < WO) {
            const float val = sa0[rl][c] + sa1[rl][c + 1] +
                              sa2[rl + 1][c] + sa3[rl + 1][c + 1];
            atomicAdd(out + (b * HO + r) * WO + c, val);
        }
    }
}

extern "C" void kernel_launch(void* const* d_in, const int* in_sizes, int n_in,
                              void* d_out, int out_size)
{
    const float* x  = (const float*)d_in[0];
    const float* bw = (const float*)d_in[1];
    const float* sw = (const float*)d_in[2];
    const float* ss = (const float*)d_in[3];
    const float* gr = (const float*)d_in[4];
    float* out = (float*)d_out;

    (void)in_sizes; (void)n_in;

    cudaMemsetAsync(out, 0, (size_t)out_size * sizeof(float));

    dim3 gs(NSTRIP, NB, CSPLIT);   // 22 x 8 x 4 = 704 blocks (one full wave)
    kan_fused_kernel<<<gs, 256>>>(x, bw, sw, ss, gr, out);
}

// round 7
// speedup vs baseline: 1.0173x; 1.0173x over previous
#include <cuda_runtime.h>
#include <cstdint>

#define WD 128
#define HT 128
#define NB 8
#define NC 16
#define HW (HT*WD)
#define CHW (NC*HW)
#define HO 127
#define WO 127
#define TR 5            // eval rows per strip (no halo)
#define NSTRIP 26       // 26*5 = 130 >= 128
#define CSPLIT 4
#define CPER (NC/CSPLIT)
#define NCELLS 12

typedef unsigned long long ull;

__device__ __forceinline__ ull pack2(float x, float y) {
    ull r; asm("mov.b64 %0, {%1, %2};" : "=l"(r) : "f"(x), "f"(y)); return r;
}
__device__ __forceinline__ void unpack2(float& x, float& y, ull v) {
    asm("mov.b64 {%0, %1}, %2;" : "=f"(x), "=f"(y) : "l"(v));
}
__device__ __forceinline__ ull fma2(ull a, ull b, ull c) {
    ull d; asm("fma.rn.f32x2 %0, %1, %2, %3;" : "=l"(d) : "l"(a), "l"(b), "l"(c)); return d;
}
__device__ __forceinline__ ull add2(ull a, ull b) {
    ull d; asm("add.rn.f32x2 %0, %1, %2;" : "=l"(d) : "l"(a), "l"(b)); return d;
}
__device__ __forceinline__ void lds_row(ull& lo, ull& hi, unsigned addr) {
    asm volatile("ld.shared.v2.u64 {%0, %1}, [%2];" : "=l"(lo), "=l"(hi) : "r"(addr));
}

__global__ void __launch_bounds__(256, 6) kan_fused_kernel(
    const float* __restrict__ x,
    const float* __restrict__ base_weight,
    const float* __restrict__ spline_weight,
    const float* __restrict__ spline_scaler,
    const float* __restrict__ grid,
    float* __restrict__ out)
{
    // Per-lane-replicated power-basis table: cell t (0..10):
    // spline(u) = A + B u + C u^2 + D u^3 per tap. Cell 11 = zeros. 24.5 KB.
    __shared__ float4 tab[NCELLS * 4 * 32];
    __shared__ float4 staging[NCELLS * 4];
    // Tap planes for this strip's 5 eval rows (10.2 KB).
    __shared__ float sa0[TR][WD];
    __shared__ float sa1[TR][WD];
    __shared__ float sa2[TR][WD];
    __shared__ float sa3[TR][WD];

    const int tid = threadIdx.x;

    // ── Stage 1: compute 48 coefficient float4s once ──
    if (tid < NCELLS * 4) {
        const int t = tid >> 2;
        const int k = tid & 3;
        float4 val = make_float4(0.f, 0.f, 0.f, 0.f);
        if (t <= 10) {
            float o[4];
#pragma unroll
            for (int f = 0; f < 4; f++) {
                const float sc = spline_scaler[f];
                float c[4];
#pragma unroll
                for (int jj = 0; jj < 4; jj++) {
                    const int idx = t - 3 + jj;
                    c[jj] = (idx >= 0 && idx < 8)
                          ? spline_weight[f * 8 + idx] * sc : 0.f;
                }
                float r;
                if (k == 0)      r = (c[0] + 4.f * c[1] + c[2]) * (1.f / 6.f);
                else if (k == 1) r = (c[2] - c[0]) * 0.5f;
                else if (k == 2) r = (c[0] - 2.f * c[1] + c[2]) * 0.5f;
                else             r = (3.f * (c[1] - c[2]) + c[3] - c[0]) * (1.f / 6.f);
                o[f] = r;
            }
            val = make_float4(o[0], o[1], o[2], o[3]);
        }
        staging[tid] = val;
    }
    __syncthreads();
    // ── Stage 2: replicate across lanes ──
#pragma unroll
    for (int e = tid; e < NCELLS * 4 * 32; e += 256)
        tab[e] = staging[e >> 5];
    __syncthreads();

    const float bw0 = __ldg(base_weight + 0);
    const float bw1 = __ldg(base_weight + 1);
    const float bw2 = __ldg(base_weight + 2);
    const float bw3 = __ldg(base_weight + 3);
    const float g0   = __ldg(grid + 0);
    const float invh = 1.0f / (__ldg(grid + 1) - g0);
    const float off0 = -g0 * invh;

    const ull bw01 = pack2(bw0, bw1);
    const ull bw23 = pack2(bw2, bw3);

    const int r0  = blockIdx.x * TR;
    const int b   = blockIdx.y;
    const int ch0 = blockIdx.z * CPER;

    const unsigned tab_base =
        (unsigned)__cvta_generic_to_shared(tab) + (unsigned)((tid & 31) * 16);

    // ── Eval: 5 rows x 128 cols, CPER channels summed (no halo) ──
    for (int e = tid; e < TR * WD; e += 256) {
        const int rl  = e >> 7;
        const int c   = e & (WD - 1);
        const int row = r0 + rl;

        ull acc01 = 0ull, acc23 = 0ull;
        if (row < HT) {
            const float* xp = x + b * CHW + ch0 * HW + row * WD + c;
            float v[CPER];
#pragma unroll
            for (int q = 0; q < CPER; q++)          // front-batched: MLP=CPER
                v[q] = __ldg(xp + q * HW);

#pragma unroll
            for (int q = 0; q < CPER; q++) {
                const float vv = v[q];
                const float pp = fmaf(vv, invh, off0);
                const float fc = floorf(pp);
                const float u  = pp - fc;
                const int cell = (int)fc;
                const int cb   = ((unsigned)cell <= 10u) ? cell : 11;

                const unsigned a = tab_base + ((unsigned)cb << 11);
                ull A01, A23, B01, B23, C01, C23, D01, D23;
                lds_row(A01, A23, a);
                lds_row(B01, B23, a + 512);
                lds_row(C01, C23, a + 1024);
                lds_row(D01, D23, a + 1536);

                const ull u2  = pack2(u, u);
                const ull t01 = fma2(fma2(fma2(D01, u2, C01), u2, B01), u2, A01);
                const ull t23 = fma2(fma2(fma2(D23, u2, C23), u2, B23), u2, A23);

                const float s = __fdividef(vv, 1.f + __expf(-vv));
                const ull s2 = pack2(s, s);
                acc01 = fma2(s2, bw01, acc01);
                acc23 = fma2(s2, bw23, acc23);
                acc01 = add2(acc01, t01);
                acc23 = add2(acc23, t23);
            }
        }
        float a0, a1, a2, a3;
        unpack2(a0, a1, acc01);
        unpack2(a2, a3, acc23);
        sa0[rl][c] = a0;
        sa1[rl][c] = a1;
        sa2[rl][c] = a2;
        sa3[rl][c] = a3;
    }

    __syncthreads();

    // ── Scatter-combine: out row r takes a0/a1 from eval row r,
    //    a2/a3 from eval row r+1 (owned by the next strip's first row). ──
#pragma unroll
    for (int o = tid; o < TR * WD; o += 256) {
        const int rl = o >> 7;
        const int c  = o & (WD - 1);
        const int r  = r0 + rl;
        if (c < WO) {
            if (r < HO) {
                const float v1 = sa0[rl][c] + sa1[rl][c + 1];
                atomicAdd(out + (b * HO + r) * WO + c, v1);
            }
            if (r >= 1 && r - 1 < HO) {
                const float v2 = sa2[rl][c] + sa3[rl][c + 1];
                atomicAdd(out + (b * HO + (r - 1)) * WO + c, v2);
            }
        }
    }
}

extern "C" void kernel_launch(void* const* d_in, const int* in_sizes, int n_in,
                              void* d_out, int out_size)
{
    const float* x  = (const float*)d_in[0];
    const float* bw = (const float*)d_in[1];
    const float* sw = (const float*)d_in[2];
    const float* ss = (const float*)d_in[3];
    const float* gr = (const float*)d_in[4];
    float* out = (float*)d_out;

    (void)in_sizes; (void)n_in;

    cudaMemsetAsync(out, 0, (size_t)out_size * sizeof(float));

    dim3 gs(NSTRIP, NB, CSPLIT);   // 26 x 8 x 4 = 832 blocks (one wave @ 6/SM)
    kan_fused_kernel<<<gs, 256>>>(x, bw, sw, ss, gr, out);
}

// round 8
// speedup vs baseline: 1.1775x; 1.1575x over previous
#include <cuda_runtime.h>
#include <cstdint>

#define WD 128
#define HT 128
#define NB 8
#define NC 16
#define HW (HT*WD)
#define CHW (NC*HW)
#define HO 127
#define WO 127
#define TS 16            // output tile (TS x TS)
#define ES 17            // eval patch (ES x ES)
#define NCELLS 12

typedef unsigned long long ull;

__device__ __forceinline__ ull pack2(float x, float y) {
    ull r; asm("mov.b64 %0, {%1, %2};" : "=l"(r) : "f"(x), "f"(y)); return r;
}
__device__ __forceinline__ void unpack2(float& x, float& y, ull v) {
    asm("mov.b64 {%0, %1}, %2;" : "=f"(x), "=f"(y) : "l"(v));
}
__device__ __forceinline__ ull fma2(ull a, ull b, ull c) {
    ull d; asm("fma.rn.f32x2 %0, %1, %2, %3;" : "=l"(d) : "l"(a), "l"(b), "l"(c)); return d;
}
__device__ __forceinline__ ull add2(ull a, ull b) {
    ull d; asm("add.rn.f32x2 %0, %1, %2;" : "=l"(d) : "l"(a), "l"(b)); return d;
}
__device__ __forceinline__ void lds_row(ull& lo, ull& hi, unsigned addr) {
    asm volatile("ld.shared.v2.u64 {%0, %1}, [%2];" : "=l"(lo), "=l"(hi) : "r"(addr));
}

__global__ void __launch_bounds__(256, 5) kan_tile_kernel(
    const float* __restrict__ x,
    const float* __restrict__ base_weight,
    const float* __restrict__ spline_weight,
    const float* __restrict__ spline_scaler,
    const float* __restrict__ grid,
    float* __restrict__ out)
{
    // Per-lane-replicated power-basis table: cell t (0..10):
    // spline(u) = A + B u + C u^2 + D u^3 per tap. Cell 11 = zeros. 24.5 KB.
    __shared__ float4 tab[NCELLS * 4 * 32];
    __shared__ float4 staging[NCELLS * 4];
    // Tap planes for the 17x17 eval patch (4.6 KB).
    __shared__ float sa0[ES][ES];
    __shared__ float sa1[ES][ES];
    __shared__ float sa2[ES][ES];
    __shared__ float sa3[ES][ES];

    const int tid = threadIdx.x;

    // ── Table build: 48 threads compute, all replicate ──
    if (tid < NCELLS * 4) {
        const int t = tid >> 2;
        const int k = tid & 3;
        float4 val = make_float4(0.f, 0.f, 0.f, 0.f);
        if (t <= 10) {
            float o[4];
#pragma unroll
            for (int f = 0; f < 4; f++) {
                const float sc = spline_scaler[f];
                float c[4];
#pragma unroll
                for (int jj = 0; jj < 4; jj++) {
                    const int idx = t - 3 + jj;
                    c[jj] = (idx >= 0 && idx < 8)
                          ? spline_weight[f * 8 + idx] * sc : 0.f;
                }
                float r;
                if (k == 0)      r = (c[0] + 4.f * c[1] + c[2]) * (1.f / 6.f);
                else if (k == 1) r = (c[2] - c[0]) * 0.5f;
                else if (k == 2) r = (c[0] - 2.f * c[1] + c[2]) * 0.5f;
                else             r = (3.f * (c[1] - c[2]) + c[3] - c[0]) * (1.f / 6.f);
                o[f] = r;
            }
            val = make_float4(o[0], o[1], o[2], o[3]);
        }
        staging[tid] = val;
    }
    __syncthreads();
#pragma unroll
    for (int e = tid; e < NCELLS * 4 * 32; e += 256)
        tab[e] = staging[e >> 5];
    __syncthreads();

    const float bw0 = __ldg(base_weight + 0);
    const float bw1 = __ldg(base_weight + 1);
    const float bw2 = __ldg(base_weight + 2);
    const float bw3 = __ldg(base_weight + 3);
    const float g0   = __ldg(grid + 0);
    const float invh = 1.0f / (__ldg(grid + 1) - g0);
    const float off0 = -g0 * invh;

    const int c0 = blockIdx.x * TS;
    const int r0 = blockIdx.y * TS;
    const int b  = blockIdx.z;

    const unsigned tab_base =
        (unsigned)__cvta_generic_to_shared(tab) + (unsigned)((tid & 31) * 16);

    // ── Eval: 17x17 patch, 16 channels summed ──
#pragma unroll
    for (int kk = 0; kk < 2; kk++) {
        const int e = tid + kk * 256;
        if (e < ES * ES) {
            const int rl = (e * 241) >> 12;   // e / 17 for e <= 288
            const int cl = e - rl * 17;
            const int row = r0 + rl;
            const int col = c0 + cl;

            ull acc01 = 0ull, acc23 = 0ull;
            float ssum = 0.f;

            if (row < HT && col < WD) {
                const float* xp = x + b * CHW + row * WD + col;
#pragma unroll
                for (int h = 0; h < 2; h++) {
                    float v[8];
#pragma unroll
                    for (int q = 0; q < 8; q++)       // front-batched: MLP=8
                        v[q] = __ldg(xp + (h * 8 + q) * HW);

#pragma unroll
                    for (int q = 0; q < 8; q++) {
                        const float vv = v[q];
                        const float pp = fmaf(vv, invh, off0);
                        const float fc = floorf(pp);
                        const float u  = pp - fc;
                        const int cell = (int)fc;
                        const int cb   = ((unsigned)cell <= 10u) ? cell : 11;

                        const unsigned a = tab_base + ((unsigned)cb << 11);
                        ull A01, A23, B01, B23, C01, C23, D01, D23;
                        lds_row(A01, A23, a);
                        lds_row(B01, B23, a + 512);
                        lds_row(C01, C23, a + 1024);
                        lds_row(D01, D23, a + 1536);

                        const ull u2  = pack2(u, u);
                        acc01 = add2(acc01,
                            fma2(fma2(fma2(D01, u2, C01), u2, B01), u2, A01));
                        acc23 = add2(acc23,
                            fma2(fma2(fma2(D23, u2, C23), u2, B23), u2, A23));

                        ssum += __fdividef(vv, 1.f + __expf(-vv));
                    }
                }
            }
            // Apply base path once: a_f = spline_f + ssum * bw_f
            const ull sp = pack2(ssum, ssum);
            acc01 = fma2(sp, pack2(bw0, bw1), acc01);
            acc23 = fma2(sp, pack2(bw2, bw3), acc23);

            float a0, a1, a2, a3;
            unpack2(a0, a1, acc01);
            unpack2(a2, a3, acc23);
            sa0[rl][cl] = a0;
            sa1[rl][cl] = a1;
            sa2[rl][cl] = a2;
            sa3[rl][cl] = a3;
        }
    }

    __syncthreads();

    // ── Combine + direct store ──
    {
        const int ty = tid >> 4;
        const int tx = tid & 15;
        const int r = r0 + ty;
        const int c = c0 + tx;
        if (r < HO && c < WO) {
            const float val = sa0[ty][tx]     + sa1[ty][tx + 1] +
                              sa2[ty + 1][tx] + sa3[ty + 1][tx + 1];
            out[(b * HO + r) * WO + c] = val;
        }
    }
}

extern "C" void kernel_launch(void* const* d_in, const int* in_sizes, int n_in,
                              void* d_out, int out_size)
{
    const float* x  = (const float*)d_in[0];
    const float* bw = (const float*)d_in[1];
    const float* sw = (const float*)d_in[2];
    const float* ss = (const float*)d_in[3];
    const float* gr = (const float*)d_in[4];
    float* out = (float*)d_out;

    (void)in_sizes; (void)n_in; (void)out_size;

    dim3 gs(8, 8, NB);    // 512 blocks, one kernel, no memset, no atomics
    kan_tile_kernel<<<gs, 256>>>(x, bw, sw, ss, gr, out);
}

// round 9
// speedup vs baseline: 1.1834x; 1.0050x over previous
#include <cuda_runtime.h>
#include <cstdint>

#define WD 128
#define HT 128
#define NB 8
#define NC 16
#define HW (HT*WD)
#define CHW (NC*HW)
#define HO 127
#define WO 127
#define TS 16            // output tile (TS x TS)
#define ES 17            // eval patch (ES x ES)
#define NCELLS 12
#define CSTRIDE 5        // float4 stride per cell (bank-decorrelating pad)

__global__ void __launch_bounds__(256) kan_tile_kernel(
    const float* __restrict__ x,
    const float* __restrict__ base_weight,
    const float* __restrict__ spline_weight,
    const float* __restrict__ spline_scaler,
    const float* __restrict__ grid,
    float* __restrict__ out)
{
    // Power-basis table, NOT lane-replicated: cell t (0..10):
    // spline(u) = A + B u + C u^2 + D u^3 per tap (float4 over taps).
    // tab4[t*CSTRIDE + k], k=0..3; stride 5 => cells 0..7 hit disjoint bank
    // quartets (cell*20 mod 32 distinct), same-cell lanes broadcast. 960 B.
    __shared__ float4 tab4[NCELLS * CSTRIDE];
    // Tap planes for the 17x17 eval patch (4.6 KB).
    __shared__ float sa0[ES][ES];
    __shared__ float sa1[ES][ES];
    __shared__ float sa2[ES][ES];
    __shared__ float sa3[ES][ES];

    const int tid = threadIdx.x;

    // ── Table build: 48 threads, one float4 each ──
    if (tid < NCELLS * 4) {
        const int t = tid >> 2;
        const int k = tid & 3;
        float4 val = make_float4(0.f, 0.f, 0.f, 0.f);
        if (t <= 10) {
            float o[4];
#pragma unroll
            for (int f = 0; f < 4; f++) {
                const float sc = spline_scaler[f];
                float c[4];
#pragma unroll
                for (int jj = 0; jj < 4; jj++) {
                    const int idx = t - 3 + jj;
                    c[jj] = (idx >= 0 && idx < 8)
                          ? spline_weight[f * 8 + idx] * sc : 0.f;
                }
                float r;
                if (k == 0)      r = (c[0] + 4.f * c[1] + c[2]) * (1.f / 6.f);
                else if (k == 1) r = (c[2] - c[0]) * 0.5f;
                else if (k == 2) r = (c[0] - 2.f * c[1] + c[2]) * 0.5f;
                else             r = (3.f * (c[1] - c[2]) + c[3] - c[0]) * (1.f / 6.f);
                o[f] = r;
            }
            val = make_float4(o[0], o[1], o[2], o[3]);
        }
        tab4[t * CSTRIDE + k] = val;
    }
    __syncthreads();

    const float bw0 = __ldg(base_weight + 0);
    const float bw1 = __ldg(base_weight + 1);
    const float bw2 = __ldg(base_weight + 2);
    const float bw3 = __ldg(base_weight + 3);
    const float g0   = __ldg(grid + 0);
    const float invh = 1.0f / (__ldg(grid + 1) - g0);
    const float off0 = -g0 * invh;

    const int c0 = blockIdx.x * TS;
    const int r0 = blockIdx.y * TS;
    const int b  = blockIdx.z;

    // ── Eval: 17x17 patch, 16 channels summed ──
    for (int e = tid; e < ES * ES; e += 256) {
        const int rl = (e * 241) >> 12;   // e/17 for e <= 288
        const int cl = e - rl * 17;
        const int row = r0 + rl;
        const int col = c0 + cl;

        float a0 = 0.f, a1 = 0.f, a2 = 0.f, a3 = 0.f;
        float ssum = 0.f;

        if (row < HT && col < WD) {
            const float* xp = x + b * CHW + row * WD + col;
#pragma unroll
            for (int h = 0; h < 2; h++) {
                float v[8];
#pragma unroll
                for (int q = 0; q < 8; q++)          // front-batched loads
                    v[q] = __ldg(xp + (h * 8 + q) * HW);

#pragma unroll
                for (int q = 0; q < 8; q++) {
                    const float vv = v[q];
                    const float pp = fmaf(vv, invh, off0);
                    const float fc = floorf(pp);
                    const float u  = pp - fc;
                    const int cell = (int)fc;
                    const int cb   = ((unsigned)cell <= 10u) ? cell : 11;

                    const float4* tp = tab4 + cb * CSTRIDE;
                    const float4 A = tp[0];
                    const float4 Bc = tp[1];
                    const float4 Cc = tp[2];
                    const float4 Dc = tp[3];

                    a0 += fmaf(fmaf(fmaf(Dc.x, u, Cc.x), u, Bc.x), u, A.x);
                    a1 += fmaf(fmaf(fmaf(Dc.y, u, Cc.y), u, Bc.y), u, A.y);
                    a2 += fmaf(fmaf(fmaf(Dc.z, u, Cc.z), u, Bc.z), u, A.z);
                    a3 += fmaf(fmaf(fmaf(Dc.w, u, Cc.w), u, Bc.w), u, A.w);

                    ssum += __fdividef(vv, 1.f + __expf(-vv));
                }
            }
        }
        // Base path applied once: a_f += ssum * bw_f
        a0 = fmaf(ssum, bw0, a0);
        a1 = fmaf(ssum, bw1, a1);
        a2 = fmaf(ssum, bw2, a2);
        a3 = fmaf(ssum, bw3, a3);

        sa0[rl][cl] = a0;
        sa1[rl][cl] = a1;
        sa2[rl][cl] = a2;
        sa3[rl][cl] = a3;
    }

    __syncthreads();

    // ── Combine + direct store ──
    {
        const int ty = tid >> 4;
        const int tx = tid & 15;
        const int r = r0 + ty;
        const int c = c0 + tx;
        if (r < HO && c < WO) {
            const float val = sa0[ty][tx]     + sa1[ty][tx + 1] +
                              sa2[ty + 1][tx] + sa3[ty + 1][tx + 1];
            out[(b * HO + r) * WO + c] = val;
        }
    }
}

extern "C" void kernel_launch(void* const* d_in, const int* in_sizes, int n_in,
                              void* d_out, int out_size)
{
    const float* x  = (const float*)d_in[0];
    const float* bw = (const float*)d_in[1];
    const float* sw = (const float*)d_in[2];
    const float* ss = (const float*)d_in[3];
    const float* gr = (const float*)d_in[4];
    float* out = (float*)d_out;

    (void)in_sizes; (void)n_in; (void)out_size;

    dim3 gs(8, 8, NB);    // 512 blocks, one kernel, no memset, no atomics
    kan_tile_kernel<<<gs, 256>>>(x, bw, sw, ss, gr, out);
}